// round 16
// baseline (speedup 1.0000x reference)
#include <cuda_runtime.h>
#include <math.h>

#define B_   16
#define T_   8192
#define CF   256            // feature channels (GLU output)
#define LOUT 8196           // padded x_evs length
#define FTN  8224           // firstt entries per batch (>= LOUT + BM + 1)
#define BM   16             // bins per pooling block

// ---- output layout (flat float32, reference tuple order) ----
#define OFF_XE  0
#define OFF_LEN (B_ * CF * LOUT)                 // 33,570,816
#define OFF_BM  (OFF_LEN + B_)                   // bmoves
#define OFF_W   (OFF_BM + B_ * T_)               // weights

// ---------------- device scratch (static; no allocation) ----------------
__device__ float g_wa[512 * 9];       // BN-folded main conv weights
__device__ float g_ba[512];
__device__ float g_w1f[62 * 32];      // [(ic*31+k)*32 + c]
__device__ float g_b1f[32];
__device__ float g_w2f[480 * 32];     // [(ic*15+k)*32 + c]
__device__ float g_b2f[32];
__device__ float g_moves[B_ * T_];    // sigmoid * norm_mean
__device__ float g_w1w[B_ * T_];      // (1-frac) * weights
__device__ float g_w2w[B_ * T_];      // frac * weights
__device__ int   g_fl[B_ * T_];
__device__ int   g_firstt[B_ * FTN];  // first t with fl >= m  (init T_)
__device__ float g_feat[B_ * T_ * CF]; // [b][t][c], 128 MiB

// ======================= K0: fold BN into weights =======================
__global__ void k_setup(const float* __restrict__ conv_w,
                        const float* __restrict__ bn_g, const float* __restrict__ bn_b,
                        const float* __restrict__ bn_m, const float* __restrict__ bn_v,
                        const float* __restrict__ p1_w, const float* __restrict__ p1_b,
                        const float* __restrict__ g1, const float* __restrict__ b1,
                        const float* __restrict__ m1, const float* __restrict__ v1,
                        const float* __restrict__ p2_w, const float* __restrict__ p2_b,
                        const float* __restrict__ g2, const float* __restrict__ b2,
                        const float* __restrict__ m2, const float* __restrict__ v2)
{
    int gt  = blockIdx.x * blockDim.x + threadIdx.x;
    int nth = gridDim.x * blockDim.x;
    for (int c = gt; c < 512; c += nth) {
        float s = bn_g[c] * rsqrtf(bn_v[c] + 1e-3f);
        g_ba[c] = bn_b[c] - bn_m[c] * s;
        #pragma unroll
        for (int k = 0; k < 9; k++) g_wa[c * 9 + k] = conv_w[c * 9 + k] * s;
    }
    for (int c = gt; c < 32; c += nth) {
        float s1 = g1[c] * rsqrtf(v1[c] + 1e-5f);
        g_b1f[c] = p1_b[c] * s1 + (b1[c] - m1[c] * s1);
        for (int ic = 0; ic < 2; ic++)
            for (int k = 0; k < 31; k++)
                g_w1f[(ic * 31 + k) * 32 + c] = p1_w[(c * 2 + ic) * 31 + k] * s1;
        float s2 = g2[c] * rsqrtf(v2[c] + 1e-5f);
        g_b2f[c] = p2_b[c] * s2 + (b2[c] - m2[c] * s2);
        for (int ic = 0; ic < 32; ic++)
            for (int k = 0; k < 15; k++)
                g_w2f[(ic * 15 + k) * 32 + c] = p2_w[(c * 32 + ic) * 15 + k] * s2;
    }
}

__global__ void k_init(void)
{
    int i = blockIdx.x * blockDim.x + threadIdx.x;
    if (i < B_ * FTN) g_firstt[i] = T_;
}

// ======================= K-feat: main conv + GLU =======================
// grid (T_/64, B_), 256 threads (one per channel)
__global__ __launch_bounds__(256) void k_feat(const float* __restrict__ x)
{
    __shared__ float xs[72];
    int b  = blockIdx.y;
    int t0 = blockIdx.x * 64;
    int c  = threadIdx.x;
    const float* xb = x + b * T_;
    for (int i = c; i < 72; i += 256) {
        int gp = t0 - 4 + i;
        xs[i] = (gp >= 0 && gp < T_) ? xb[gp] : 0.f;
    }
    __syncthreads();
    float wA[9], wG[9];
    #pragma unroll
    for (int k = 0; k < 9; k++) {
        wA[k] = g_wa[c * 9 + k];
        wG[k] = g_wa[(c + 256) * 9 + k];
    }
    float bA = g_ba[c], bG = g_ba[c + 256];
    float* fo = g_feat + ((size_t)(b * T_ + t0)) * CF + c;
    for (int t = 0; t < 64; t++) {
        float a = bA, g = bG;
        #pragma unroll
        for (int k = 0; k < 9; k++) {
            float xv = xs[t + k];
            a = fmaf(wA[k], xv, a);
            g = fmaf(wG[k], xv, g);
        }
        fo[(size_t)t * CF] = a / (1.f + expf(-g));  // a * sigmoid(g)
    }
}

// ======================= K1: fused predictor =======================
// grid (T_/128, B_), 256 threads.
// s-index (stage1): global t = (T0-14)+s, s in [0,158)
// u-index (stage2): global t = (T0-7)+u,  u in [0,144)
// CRITICAL: inter-stage padding — stage outputs at global t outside [0,T)
// must be EXACTLY ZERO (they are the next conv's zero padding in the
// reference), not the value of the conv evaluated on padded x.
#define XW 192
__global__ __launch_bounds__(256) void k_pred(const float* __restrict__ x,
                                              const float* __restrict__ p3_w,
                                              const float* __restrict__ p3_b,
                                              const float* __restrict__ norm_mean,
                                              float* __restrict__ out)
{
    __shared__ float xs[2 * XW];
    __shared__ float s1s[32 * 161];
    __shared__ float s2s[144 * 33];
    int b   = blockIdx.y;
    int T0  = blockIdx.x * 128;
    int tid = threadIdx.x;
    const float* xb = x + b * T_;

    // x window [T0-29, T0+163), zero padded
    for (int i = tid; i < XW; i += 256) {
        int gp = T0 - 29 + i;
        float v = (gp >= 0 && gp < T_) ? xb[gp] : 0.f;
        xs[i] = v;
        xs[XW + i] = v * v;
    }
    __syncthreads();

    // ---- stage1: p1 conv (k=31, 2 in-ch) + BN + swish ----
    {
        int c  = tid & 31;
        int r0 = tid >> 5;   // 0..7
        float acc[20];
        float bias = g_b1f[c];
        #pragma unroll
        for (int i = 0; i < 20; i++) acc[i] = bias;
        #pragma unroll
        for (int ic = 0; ic < 2; ic++) {
            for (int k = 0; k < 31; k++) {
                float w = g_w1f[(ic * 31 + k) * 32 + c];
                #pragma unroll
                for (int i = 0; i < 20; i++)
                    acc[i] = fmaf(w, xs[ic * XW + r0 + 8 * i + k], acc[i]);
            }
        }
        #pragma unroll
        for (int i = 0; i < 20; i++) {
            int   s   = r0 + 8 * i;
            int   gt1 = T0 - 14 + s;           // global t of this stage1 value
            float v   = acc[i];
            float sg  = 1.f / (1.f + expf(-v));
            float r   = (gt1 >= 0 && gt1 < T_) ? (v * sg) : 0.f;  // pad mask
            s1s[c * 161 + s] = r;              // s up to 159 (158..159 unused)
        }
    }
    __syncthreads();

    // ---- stage2: p2 conv (k=15, 32 in-ch) + BN + swish ----
    {
        int c  = tid & 31;
        int g  = tid >> 5;
        int u0 = g * 18;     // u in [u0, u0+18)
        float acc[18];
        float bias = g_b2f[c];
        #pragma unroll
        for (int j = 0; j < 18; j++) acc[j] = bias;
        for (int ic = 0; ic < 32; ic++) {
            float r[32];
            #pragma unroll
            for (int j = 0; j < 32; j++) r[j] = s1s[ic * 161 + u0 + j];  // max 157
            #pragma unroll
            for (int k = 0; k < 15; k++) {
                float w = g_w2f[(ic * 15 + k) * 32 + c];
                #pragma unroll
                for (int j = 0; j < 18; j++) acc[j] = fmaf(w, r[j + k], acc[j]);
            }
        }
        #pragma unroll
        for (int j = 0; j < 18; j++) {
            int   gu = T0 - 7 + u0 + j;        // global t of this stage2 value
            float v  = acc[j];
            float sg = 1.f / (1.f + expf(-v));
            float r  = (gu >= 0 && gu < T_) ? (v * sg) : 0.f;     // pad mask
            s2s[(u0 + j) * 33 + c] = r;
        }
    }
    __syncthreads();

    // ---- stage3: p3 conv (k=15, 2 out-ch) + sigmoid ----
    {
        int t  = tid >> 1;   // 0..127
        int oc = tid & 1;
        float acc = p3_b[oc];
        for (int ic = 0; ic < 32; ic++) {
            #pragma unroll
            for (int k = 0; k < 15; k++)
                acc = fmaf(p3_w[(oc * 32 + ic) * 15 + k], s2s[(t + k) * 33 + ic], acc);
        }
        float sg = 1.f / (1.f + expf(-acc));
        int gt = T0 + t;
        if (oc == 0) {
            out[OFF_W + b * T_ + gt] = sg;                 // weights
        } else {
            out[OFF_BM + b * T_ + gt] = sg;                // bmoves
            g_moves[b * T_ + gt] = sg * norm_mean[0];      // moves (eval renorm)
        }
    }
}

// ======================= K2: fp32 Brent-Kung cumsum + bin tables =======================
// Same association tree as jax associative_scan (fp32) for power-of-2 length.
// one block per batch row; 256 threads
__global__ __launch_bounds__(256) void k_scan(float* __restrict__ out)
{
    __shared__ float ps[T_];
    int b   = blockIdx.x;
    int tid = threadIdx.x;
    const float* mv = g_moves + b * T_;
    for (int t = tid; t < T_; t += 256) ps[t] = mv[t];

    // up-sweep (reduce): pairwise sums
    for (int d = 1; d < T_; d <<= 1) {
        __syncthreads();
        int stride = d << 1;
        int cnt = T_ / stride;
        for (int i = tid; i < cnt; i += 256) {
            int idx = (i + 1) * stride - 1;
            ps[idx] = ps[idx - d] + ps[idx];
        }
    }
    // down-sweep: fill interior prefixes
    for (int d = T_ >> 2; d >= 1; d >>= 1) {
        __syncthreads();
        int stride = d << 1;
        int cnt = T_ / stride - 1;
        for (int i = tid; i < cnt; i += 256) {
            int idx = (i + 1) * stride - 1 + d;
            ps[idx] = ps[idx - d] + ps[idx];
        }
    }
    __syncthreads();

    const float* wt = out + OFF_W + b * T_;
    for (int t = tid; t < T_; t += 256) {
        float pf   = ps[t];
        float flo  = floorf(pf);
        float frac = pf - flo;
        int   fl   = (int)flo;
        float w    = wt[t];
        g_fl[b * T_ + t]  = fl;
        g_w1w[b * T_ + t] = (1.f - frac) * w;
        g_w2w[b * T_ + t] = frac * w;
        int fp = (t == 0) ? -1 : (int)floorf(ps[t - 1]);
        if (fl > fp) g_firstt[b * FTN + fl] = t;   // fl steps by 0 or +1 (moves < 1)
    }
    if (tid == 0) out[OFF_LEN + b] = floorf(ps[T_ - 1]) + 2.f;   // lens = fl[-1] + 2
}

// ======================= K3: gather pooling (zero atomics) =======================
// grid (ceil(LOUT/BM), B_), 256 threads (one per channel)
__global__ __launch_bounds__(256) void k_pool(float* __restrict__ out)
{
    __shared__ float acc_s[BM][257];
    int b  = blockIdx.y;
    int m0 = blockIdx.x * BM;
    int c  = threadIdx.x;
    for (int i = c; i < BM * 257; i += 256) ((float*)acc_s)[i] = 0.f;
    __syncthreads();

    const int* ft = g_firstt + b * FTN;
    int tstart = ft[(m0 > 0) ? (m0 - 1) : 0];
    int tend   = ft[m0 + BM];
    const int*   flb = g_fl  + b * T_;
    const float* w1b = g_w1w + b * T_;
    const float* w2b = g_w2w + b * T_;
    const float* fb  = g_feat + (size_t)b * T_ * CF;

    if (tstart < tend) {
        float accA = 0.f, accB = 0.f;
        int cb = flb[tstart];
        // 1-deep prefetch (feat load is the DRAM-latency one)
        float fvn = fb[(size_t)tstart * CF + c];
        int   fn  = cb;
        float w1n = w1b[tstart], w2n = w2b[tstart];
        for (int t = tstart; t < tend; t++) {
            float fv = fvn; int f = fn; float w1v = w1n, w2v = w2n;
            int tn = t + 1;
            if (tn < tend) {
                fvn = fb[(size_t)tn * CF + c];
                fn  = flb[tn];
                w1n = w1b[tn];
                w2n = w2b[tn];
            }
            if (f != cb) {            // fl advanced by exactly 1: bin cb complete
                if (cb >= m0) acc_s[cb - m0][c] = accA;
                accA = accB;
                accB = 0.f;
                cb = f;
            }
            accA = fmaf(w1v, fv, accA);   // -> bin fl[t]
            accB = fmaf(w2v, fv, accB);   // -> bin fl[t]+1
        }
        if (cb >= m0 && cb < m0 + BM)         acc_s[cb - m0][c]     = accA;
        if (cb + 1 >= m0 && cb + 1 < m0 + BM) acc_s[cb + 1 - m0][c] = accB;
    }
    __syncthreads();

    // x_evs[b][ch][m0+m]
    for (int i = c; i < CF * BM; i += 256) {
        int ch = i >> 4;
        int m  = i & (BM - 1);
        int gm = m0 + m;
        if (gm < LOUT)
            out[OFF_XE + ((size_t)(b * CF + ch)) * LOUT + gm] = acc_s[m][ch];
    }
}

// ======================= launch =======================
extern "C" void kernel_launch(void* const* d_in, const int* in_sizes, int n_in,
                              void* d_out, int out_size)
{
    const float* x      = (const float*)d_in[0];
    const float* conv_w = (const float*)d_in[1];
    const float* bn_g   = (const float*)d_in[2];
    const float* bn_b   = (const float*)d_in[3];
    const float* bn_m   = (const float*)d_in[4];
    const float* bn_v   = (const float*)d_in[5];
    const float* p1_w   = (const float*)d_in[6];
    const float* p1_b   = (const float*)d_in[7];
    const float* g1     = (const float*)d_in[8];
    const float* b1     = (const float*)d_in[9];
    const float* m1     = (const float*)d_in[10];
    const float* v1     = (const float*)d_in[11];
    const float* p2_w   = (const float*)d_in[12];
    const float* p2_b   = (const float*)d_in[13];
    const float* g2     = (const float*)d_in[14];
    const float* b2     = (const float*)d_in[15];
    const float* m2     = (const float*)d_in[16];
    const float* v2     = (const float*)d_in[17];
    const float* p3_w   = (const float*)d_in[18];
    const float* p3_b   = (const float*)d_in[19];
    const float* nmean  = (const float*)d_in[20];
    float* out = (float*)d_out;

    k_setup<<<2, 256>>>(conv_w, bn_g, bn_b, bn_m, bn_v,
                        p1_w, p1_b, g1, b1, m1, v1,
                        p2_w, p2_b, g2, b2, m2, v2);
    k_init<<<(B_ * FTN + 255) / 256, 256>>>();
    k_feat<<<dim3(T_ / 64, B_), 256>>>(x);
    k_pred<<<dim3(T_ / 128, B_), 256>>>(x, p3_w, p3_b, nmean, out);
    k_scan<<<B_, 256>>>(out);
    k_pool<<<dim3((LOUT + BM - 1) / BM, B_), 256>>>(out);
}